// round 3
// baseline (speedup 1.0000x reference)
#include <cuda_runtime.h>

// Blur: depthwise 4x4 FIR (separable [1,3,3,1] ⊗ [1,3,3,1] / 16), pad (1,1).
// Input (4,128,513,513) f32 -> Output (4,128,512,512) f32.
//
// Round-3: software-pipelined row staging. Each warp owns a 128-col output
// strip; per row it stages a 131-float window into warp-private smem via 5
// coalesced LDG.32 (prefetched into registers one row ahead so DRAM latency
// is hidden behind hcalc/STG/sync of the previous row). Horizontal FIR from
// two aligned LDS.128/thread (4 cols/thread); vertical FIR in a 4-entry
// register ring; one STG.128/thread/row. Boundary handling via per-lane
// predicated loads (no mask arithmetic, no OOB touches).

#define W_IN   513
#define H_IN   513
#define W_OUT  512
#define H_OUT  512
#define STRIP  64
#define BUFSZ  160      // 132 used; padded to keep stores unconditional
#define NPLANE 512      // 4*128

__global__ __launch_bounds__(128, 12)
void blur_pipe_kernel(const float* __restrict__ in, float* __restrict__ out)
{
    __shared__ float sbuf[4][2][BUFSZ];   // [warp][double-buffer][idx]

    const int tid   = threadIdx.x;
    const int warp  = tid >> 5;
    const int lane  = tid & 31;
    const int plane = blockIdx.y;
    const int y0    = blockIdx.x * STRIP;
    const int wx0   = warp << 7;          // warp's first output col

    const float* ip = in  + (size_t)plane * (W_IN  * H_IN);
    float*       op = out + (size_t)plane * (W_OUT * H_OUT);

    // Window: buf[i] = in[row][wx0 - 1 + i], i in [0,131). Lane handles
    // idx = lane + 32k. Only k=0 (left edge, warp0 lane0) and k=4
    // (idx>=131, or right edge) can be out of range -> predicated loads.
    const int  goff = wx0 - 1 + lane;                    // col for k=0
    const bool m0   = (goff >= 0);
    const bool m4   = (lane < 3) && (goff + 128 < W_IN);

    float* __restrict__ buf0 = &sbuf[warp][0][0];
    float* __restrict__ buf1 = &sbuf[warp][1][0];

    float v0, v1, v2, v3, v4;             // prefetch registers (one row)

    auto ldrow = [&](int r) {
        if ((unsigned)r < (unsigned)H_IN) {              // warp-uniform
            const float* __restrict__ rp = ip + (size_t)r * W_IN + goff;
            v0 = m0 ? __ldg(rp)       : 0.0f;
            v1 = __ldg(rp + 32);
            v2 = __ldg(rp + 64);
            v3 = __ldg(rp + 96);
            v4 = m4 ? __ldg(rp + 128) : 0.0f;
        } else {
            v0 = v1 = v2 = v3 = v4 = 0.0f;               // pad rows
        }
    };

    auto strow = [&](float* __restrict__ buf) {
        buf[lane      ] = v0;
        buf[lane +  32] = v1;
        buf[lane +  64] = v2;
        buf[lane +  96] = v3;
        buf[lane + 128] = v4;
    };

    // Horizontal FIR: window buf[4l .. 4l+6] = in[x0-1 .. x0+5], x0 = wx0+4l.
    auto hcalc = [&](const float* __restrict__ buf) -> float4 {
        float4 a = *reinterpret_cast<const float4*>(buf + 4 * lane);       // x0-1..x0+2
        float4 c = *reinterpret_cast<const float4*>(buf + 4 * lane + 4);   // x0+3..x0+6
        float4 h;
        h.x = a.x + 3.0f * (a.y + a.z) + a.w;
        h.y = a.y + 3.0f * (a.z + a.w) + c.x;
        h.z = a.z + 3.0f * (a.w + c.x) + c.y;
        h.w = a.w + 3.0f * (c.x + c.y) + c.z;
        return h;
    };

    float4 h[4];
    // Pipelined prologue: rows y0-1, y0, y0+1 staged; row y0+2 in flight.
    ldrow(y0 - 1); strow(buf0);
    ldrow(y0);
    __syncwarp();  h[0] = hcalc(buf0);
    strow(buf1);   ldrow(y0 + 1);
    __syncwarp();  h[1] = hcalc(buf1);
    strow(buf0);   ldrow(y0 + 2);
    __syncwarp();  h[2] = hcalc(buf0);

    #pragma unroll 4
    for (int i = 0; i < STRIP; ++i) {
        float* __restrict__ buf = (i & 1) ? buf0 : buf1;
        strow(buf);               // commit row y0+2+i (in v*)
        ldrow(y0 + 3 + i);        // prefetch next row: latency hidden below
        __syncwarp();
        float4 hd = hcalc(buf);
        h[(i + 3) & 3] = hd;
        float4 ha = h[ i      & 3];
        float4 hb = h[(i + 1) & 3];
        float4 hc = h[(i + 2) & 3];

        float4 o;
        o.x = (ha.x + hd.x + 3.0f * (hb.x + hc.x)) * 0.0625f;
        o.y = (ha.y + hd.y + 3.0f * (hb.y + hc.y)) * 0.0625f;
        o.z = (ha.z + hd.z + 3.0f * (hb.z + hc.z)) * 0.0625f;
        o.w = (ha.w + hd.w + 3.0f * (hb.w + hc.w)) * 0.0625f;

        *reinterpret_cast<float4*>(op + (size_t)(y0 + i) * W_OUT + wx0 + 4 * lane) = o;
    }
}

extern "C" void kernel_launch(void* const* d_in, const int* in_sizes, int n_in,
                              void* d_out, int out_size)
{
    const float* in  = (const float*)d_in[0];
    float*       out = (float*)d_out;
    // d_in[1] is the 4x4 FIR buffer: fixed normalized [1,3,3,1] outer product
    // * factor^2 == ([1,3,3,1] ⊗ [1,3,3,1]) / 16, folded into the constants.

    dim3 grid(H_OUT / STRIP, NPLANE);   // (8, 512)
    blur_pipe_kernel<<<grid, 128>>>(in, out);
}